// round 10
// baseline (speedup 1.0000x reference)
#include <cuda_runtime.h>
#include <math.h>

#define N_NODES 50000
#define N_EDGES 1600000
#define IN_DIM  128
#define HID     64
#define EPS     1e-6f

// ---------------- device scratch (static; 16B-aligned) ----------------
__device__ __align__(16) int   g_csrc[N_EDGES];     // CSR: src grouped by dst
__device__ __align__(16) int   g_edst[N_EDGES];     // dst (int32)
__device__ __align__(16) int   g_esrc[N_EDGES];     // src (int32)
__device__ __align__(16) int   g_row [N_NODES + 1]; // CSR row offsets
__device__ __align__(16) int   g_cur [N_NODES];     // scatter cursors
__device__ __align__(16) int   g_degi[N_NODES];
__device__ __align__(16) float g_invdeg[N_NODES];
__device__ __align__(16) float g_H [N_NODES * HID]; // layer output h
__device__ __align__(16) float g_Hs[N_NODES * HID]; // h @ ws
__device__ __align__(16) float g_Hn[N_NODES * HID]; // h @ wn

// ---------------- prep ----------------
// Harness dtype set is {float32, int32, bfloat16}: jnp.int64 edge_index
// arrives as int32. Read as int32; clamp defensively so no later kernel
// can ever go OOB.
__global__ void k_zero_deg() {
    int i = blockIdx.x * blockDim.x + threadIdx.x;
    if (i < N_NODES) g_degi[i] = 0;
}

__global__ void k_prep(const int* __restrict__ ei) {
    int e = blockIdx.x * blockDim.x + threadIdx.x;
    if (e >= N_EDGES) return;
    int s = ei[e];
    int d = ei[N_EDGES + e];
    s = min(max(s, 0), N_NODES - 1);
    d = min(max(d, 0), N_NODES - 1);
    g_esrc[e] = s;
    g_edst[e] = d;
    atomicAdd(&g_degi[d], 1);
}

// single-block exclusive scan of g_degi -> g_row, g_cur; also invdeg
__global__ void k_scan() {
    __shared__ int warpsums[32];
    const int CH = (N_NODES + 1023) / 1024;  // 49
    int t    = threadIdx.x;
    int lane = t & 31;
    int wid  = t >> 5;
    int base = t * CH;

    int local = 0;
    for (int i = 0; i < CH; i++) {
        int idx = base + i;
        if (idx < N_NODES) local += g_degi[idx];
    }
    int v = local;
#pragma unroll
    for (int o = 1; o < 32; o <<= 1) {
        int n = __shfl_up_sync(0xffffffffu, v, o);
        if (lane >= o) v += n;
    }
    if (lane == 31) warpsums[wid] = v;
    __syncthreads();
    if (wid == 0) {
        int w = warpsums[lane];
#pragma unroll
        for (int o = 1; o < 32; o <<= 1) {
            int n = __shfl_up_sync(0xffffffffu, w, o);
            if (lane >= o) w += n;
        }
        warpsums[lane] = w;
    }
    __syncthreads();
    int run = v - local + (wid > 0 ? warpsums[wid - 1] : 0);  // exclusive prefix
    for (int i = 0; i < CH; i++) {
        int idx = base + i;
        if (idx < N_NODES) {
            g_row[idx] = run;
            g_cur[idx] = run;
            int dg = g_degi[idx];
            g_invdeg[idx] = 1.0f / fmaxf((float)dg, 1.0f);
            run += dg;
        }
    }
    if (t == 1023) g_row[N_NODES] = N_EDGES;
}

__global__ void k_scatter() {
    int e = blockIdx.x * blockDim.x + threadIdx.x;
    if (e >= N_EDGES) return;
    int d = g_edst[e];
    int p = atomicAdd(&g_cur[d], 1);
    g_csrc[p] = g_esrc[e];
}

// ---------------- GEMM: out[N,64] = Hin[N,K] @ W[K,64] ----------------
// 256 threads = 64 cols x 4 row-groups; 16 rows per block.
// srcSel: 0 -> xin param, 1 -> g_H.  dstSel: 0 -> g_Hs, 1 -> g_Hn.
template <int K>
__global__ void k_gemm(const float* __restrict__ xin, const float* __restrict__ W,
                       int srcSel, int dstSel) {
    __shared__ float Ws[K * HID];
    __shared__ float Ht[16][K];
    const float* Hin = srcSel ? (const float*)g_H : xin;
    float* out = dstSel ? g_Hn : g_Hs;

    int t   = threadIdx.x;
    int col = t & 63;
    int rg  = t >> 6;
    int rowBase = blockIdx.x * 16;

    for (int i = t; i < K * HID; i += 256) Ws[i] = W[i];
    for (int i = t; i < 16 * K; i += 256) {
        int r = i / K, k = i % K;
        int gr = rowBase + r;
        Ht[r][k] = (gr < N_NODES) ? Hin[(size_t)gr * K + k] : 0.f;
    }
    __syncthreads();

    float acc[4] = {0.f, 0.f, 0.f, 0.f};
    for (int k = 0; k < K; k++) {
        float wv = Ws[k * HID + col];
#pragma unroll
        for (int r = 0; r < 4; r++) acc[r] += Ht[rg + 4 * r][k] * wv;
    }
#pragma unroll
    for (int r = 0; r < 4; r++) {
        int gr = rowBase + rg + 4 * r;
        if (gr < N_NODES) out[(size_t)gr * HID + col] = acc[r];
    }
}

// ---------------- fused pull-aggregate + finalize ----------------
// one warp per destination node: agg = sum Hn[src] over in-edges (registers),
// then h2 = relu(Hs + agg*invdeg); h = h2 / (||h2|| + EPS)  -> g_H
__global__ void k_aggfin() {
    unsigned gt   = blockIdx.x * blockDim.x + threadIdx.x;
    unsigned node = gt >> 5;
    unsigned lane = gt & 31;
    if (node >= N_NODES) return;

    const int* __restrict__ csrc = g_csrc;
    const float* __restrict__ Hn = g_Hn;
    int beg = g_row[node];
    int end = g_row[node + 1];
    float s0 = 0.f, s1 = 0.f;
    int i = beg;
    for (; i + 1 < end; i += 2) {
        int srcA = csrc[i];
        int srcB = csrc[i + 1];
        const float* rA = Hn + (size_t)srcA * HID;
        const float* rB = Hn + (size_t)srcB * HID;
        float a0 = __ldg(rA + lane), a1 = __ldg(rA + lane + 32);
        float b0 = __ldg(rB + lane), b1 = __ldg(rB + lane + 32);
        s0 += a0 + b0;
        s1 += a1 + b1;
    }
    if (i < end) {
        int srcA = csrc[i];
        const float* rA = Hn + (size_t)srcA * HID;
        s0 += __ldg(rA + lane);
        s1 += __ldg(rA + lane + 32);
    }

    float inv = g_invdeg[node];
    size_t base = (size_t)node * HID;
    float a0 = fmaxf(g_Hs[base + lane]      + s0 * inv, 0.f);
    float a1 = fmaxf(g_Hs[base + lane + 32] + s1 * inv, 0.f);
    float ss = a0 * a0 + a1 * a1;
#pragma unroll
    for (int o = 16; o > 0; o >>= 1) ss += __shfl_xor_sync(0xffffffffu, ss, o);
    float r = 1.f / (sqrtf(ss) + EPS);
    g_H[base + lane]      = a0 * r;
    g_H[base + lane + 32] = a1 * r;
}

// ---------------- MLP head: sigmoid(relu(H@mw1+mb1)@mw2+mb2) ----------------
__global__ void k_mlp(const float* __restrict__ mw1, const float* __restrict__ mb1,
                      const float* __restrict__ mw2, const float* __restrict__ mb2,
                      float* __restrict__ out) {
    __shared__ float W1[HID * 32];
    __shared__ float W2[32];
    __shared__ float B1[32];
    __shared__ float hrow[8][HID];
    int t = threadIdx.x;
    for (int i = t; i < HID * 32; i += 256) W1[i] = mw1[i];
    if (t < 32) { W2[t] = mw2[t]; B1[t] = mb1[t]; }
    __syncthreads();

    int wid = t >> 5, lane = t & 31;
    int node = blockIdx.x * 8 + wid;
    if (node >= N_NODES) return;
    size_t base = (size_t)node * HID;
    hrow[wid][lane]      = g_H[base + lane];
    hrow[wid][lane + 32] = g_H[base + lane + 32];
    __syncwarp();

    float acc = B1[lane];
    for (int k = 0; k < HID; k++) acc += hrow[wid][k] * W1[k * 32 + lane];
    acc = fmaxf(acc, 0.f) * W2[lane];
#pragma unroll
    for (int o = 16; o > 0; o >>= 1) acc += __shfl_xor_sync(0xffffffffu, acc, o);
    if (lane == 0) out[node] = 1.f / (1.f + expf(-(acc + mb2[0])));
}

// ---------------- launch (pure kernel launches; nothing else) ----------------
extern "C" void kernel_launch(void* const* d_in, const int* in_sizes, int n_in,
                              void* d_out, int out_size) {
    const float* x   = (const float*)d_in[0];
    const int*   ei  = (const int*)d_in[1];     // int32 (harness dtype set)
    const float* w0s = (const float*)d_in[2];
    const float* w0n = (const float*)d_in[3];
    const float* w1s = (const float*)d_in[4];
    const float* w1n = (const float*)d_in[5];
    const float* w2s = (const float*)d_in[6];
    const float* w2n = (const float*)d_in[7];
    const float* mw1 = (const float*)d_in[8];
    const float* mb1 = (const float*)d_in[9];
    const float* mw2 = (const float*)d_in[10];
    const float* mb2 = (const float*)d_in[11];
    float*       out = (float*)d_out;

    const int TB = 256;
    // CSR build
    k_zero_deg<<<(N_NODES + TB - 1) / TB, TB>>>();
    k_prep<<<(N_EDGES + TB - 1) / TB, TB>>>(ei);
    k_scan<<<1, 1024>>>();
    k_scatter<<<(N_EDGES + TB - 1) / TB, TB>>>();

    const int gemmBlocks = (N_NODES + 15) / 16;
    const int aggBlocks  = (N_NODES * 32 + TB - 1) / TB;

    // layer 0 (K = 128, input = x)
    k_gemm<IN_DIM><<<gemmBlocks, TB>>>(x, w0n, 0, 1);
    k_gemm<IN_DIM><<<gemmBlocks, TB>>>(x, w0s, 0, 0);
    k_aggfin<<<aggBlocks, TB>>>();

    // layer 1
    k_gemm<HID><<<gemmBlocks, TB>>>(nullptr, w1n, 1, 1);
    k_gemm<HID><<<gemmBlocks, TB>>>(nullptr, w1s, 1, 0);
    k_aggfin<<<aggBlocks, TB>>>();

    // layer 2
    k_gemm<HID><<<gemmBlocks, TB>>>(nullptr, w2n, 1, 1);
    k_gemm<HID><<<gemmBlocks, TB>>>(nullptr, w2s, 1, 0);
    k_aggfin<<<aggBlocks, TB>>>();

    // MLP head
    k_mlp<<<(N_NODES + 7) / 8, TB>>>(mw1, mb1, mw2, mb2, out);
}

// round 13
// speedup vs baseline: 1.3231x; 1.3231x over previous
#include <cuda_runtime.h>
#include <math.h>

#define N_NODES 50000
#define N_EDGES 1600000
#define IN_DIM  128
#define HID     64
#define EPS     1e-6f

// ---------------- device scratch (static; 16B-aligned) ----------------
__device__ __align__(16) int   g_csrc[N_EDGES];     // CSR: src grouped by dst
__device__ __align__(16) int   g_edst[N_EDGES];     // dst (int32)
__device__ __align__(16) int   g_esrc[N_EDGES];     // src (int32)
__device__ __align__(16) int   g_row [N_NODES + 1]; // CSR row offsets
__device__ __align__(16) int   g_cur [N_NODES];     // scatter cursors
__device__ __align__(16) int   g_degi[N_NODES];
__device__ __align__(16) float g_invdeg[N_NODES];
__device__ __align__(16) float g_H [N_NODES * HID]; // layer output h
__device__ __align__(16) float g_Hs[N_NODES * HID]; // h @ ws
__device__ __align__(16) float g_Hn[N_NODES * HID]; // h @ wn

// ---------------- prep ----------------
__global__ void k_zero_deg() {
    int i = blockIdx.x * blockDim.x + threadIdx.x;
    if (i < N_NODES) g_degi[i] = 0;
}

__global__ void k_prep(const int* __restrict__ ei) {
    int e = blockIdx.x * blockDim.x + threadIdx.x;
    if (e >= N_EDGES) return;
    int s = ei[e];
    int d = ei[N_EDGES + e];
    s = min(max(s, 0), N_NODES - 1);
    d = min(max(d, 0), N_NODES - 1);
    g_esrc[e] = s;
    g_edst[e] = d;
    atomicAdd(&g_degi[d], 1);
}

// single-block exclusive scan of g_degi -> g_row, g_cur; also invdeg
__global__ void k_scan() {
    __shared__ int warpsums[32];
    const int CH = (N_NODES + 1023) / 1024;  // 49
    int t    = threadIdx.x;
    int lane = t & 31;
    int wid  = t >> 5;
    int base = t * CH;

    int local = 0;
    for (int i = 0; i < CH; i++) {
        int idx = base + i;
        if (idx < N_NODES) local += g_degi[idx];
    }
    int v = local;
#pragma unroll
    for (int o = 1; o < 32; o <<= 1) {
        int n = __shfl_up_sync(0xffffffffu, v, o);
        if (lane >= o) v += n;
    }
    if (lane == 31) warpsums[wid] = v;
    __syncthreads();
    if (wid == 0) {
        int w = warpsums[lane];
#pragma unroll
        for (int o = 1; o < 32; o <<= 1) {
            int n = __shfl_up_sync(0xffffffffu, w, o);
            if (lane >= o) w += n;
        }
        warpsums[lane] = w;
    }
    __syncthreads();
    int run = v - local + (wid > 0 ? warpsums[wid - 1] : 0);  // exclusive prefix
    for (int i = 0; i < CH; i++) {
        int idx = base + i;
        if (idx < N_NODES) {
            g_row[idx] = run;
            g_cur[idx] = run;
            int dg = g_degi[idx];
            g_invdeg[idx] = 1.0f / fmaxf((float)dg, 1.0f);
            run += dg;
        }
    }
    if (t == 1023) g_row[N_NODES] = N_EDGES;
}

__global__ void k_scatter() {
    int e = blockIdx.x * blockDim.x + threadIdx.x;
    if (e >= N_EDGES) return;
    int d = g_edst[e];
    int p = atomicAdd(&g_cur[d], 1);
    g_csrc[p] = g_esrc[e];
}

// ---------------- fused dual GEMM: Hs = Hin@Ws, Hn = Hin@Wn ----------------
// 64x64 output tile per block, 256 threads as 16x16; each thread computes a
// 4-row x 4-col register tile for BOTH outputs (one shared A read).
// Per k-step: 4 LDS.32 + 2 LDS.128 feed 32 FFMA -> FMA-bound.
template <int K>
__global__ void k_gemm2(const float* __restrict__ xin,
                        const float* __restrict__ Ws,
                        const float* __restrict__ Wn,
                        int srcSel) {
    __shared__ __align__(16) float sHt[64][33];   // [row][k] padded: conflict-free
    __shared__ __align__(16) float sWs[32][64];
    __shared__ __align__(16) float sWn[32][64];

    const float* Hin = srcSel ? (const float*)g_H : xin;
    int t  = threadIdx.x;
    int tx = t & 15;         // col group (4 cols)
    int ty = t >> 4;         // row group (4 rows)
    int rowBase = blockIdx.x * 64;

    float acc_s[4][4] = {{0.f}};
    float acc_n[4][4] = {{0.f}};

    for (int k0 = 0; k0 < K; k0 += 32) {
        // load H tile (coalesced k-contiguous reads; bank-conflict-free stores)
        {
            int lane = t & 31, w = t >> 5;
            for (int r = w; r < 64; r += 8) {
                int gr = rowBase + r;
                sHt[r][lane] = (gr < N_NODES) ? Hin[(size_t)gr * K + k0 + lane] : 0.f;
            }
            for (int i = t; i < 32 * 64; i += 256) {
                ((float*)sWs)[i] = Ws[k0 * HID + i];
                ((float*)sWn)[i] = Wn[k0 * HID + i];
            }
        }
        __syncthreads();

#pragma unroll
        for (int kk = 0; kk < 32; kk++) {
            float a[4];
#pragma unroll
            for (int i = 0; i < 4; i++) a[i] = sHt[ty * 4 + i][kk];
            float4 bs = *(const float4*)&sWs[kk][tx * 4];
            float4 bn = *(const float4*)&sWn[kk][tx * 4];
#pragma unroll
            for (int i = 0; i < 4; i++) {
                acc_s[i][0] += a[i] * bs.x;
                acc_s[i][1] += a[i] * bs.y;
                acc_s[i][2] += a[i] * bs.z;
                acc_s[i][3] += a[i] * bs.w;
                acc_n[i][0] += a[i] * bn.x;
                acc_n[i][1] += a[i] * bn.y;
                acc_n[i][2] += a[i] * bn.z;
                acc_n[i][3] += a[i] * bn.w;
            }
        }
        __syncthreads();
    }

#pragma unroll
    for (int i = 0; i < 4; i++) {
        int gr = rowBase + ty * 4 + i;
        if (gr < N_NODES) {
            float4 vs = make_float4(acc_s[i][0], acc_s[i][1], acc_s[i][2], acc_s[i][3]);
            float4 vn = make_float4(acc_n[i][0], acc_n[i][1], acc_n[i][2], acc_n[i][3]);
            *(float4*)&g_Hs[(size_t)gr * HID + tx * 4] = vs;
            *(float4*)&g_Hn[(size_t)gr * HID + tx * 4] = vn;
        }
    }
}

// ---------------- fused pull-aggregate + finalize ----------------
// one warp per destination node: agg = sum Hn[src] over in-edges (registers),
// then h2 = relu(Hs + agg*invdeg); h = h2 / (||h2|| + EPS)  -> g_H
__global__ void k_aggfin() {
    unsigned gt   = blockIdx.x * blockDim.x + threadIdx.x;
    unsigned node = gt >> 5;
    unsigned lane = gt & 31;
    if (node >= N_NODES) return;

    const int* __restrict__ csrc = g_csrc;
    const float* __restrict__ Hn = g_Hn;
    int beg = g_row[node];
    int end = g_row[node + 1];
    float s0 = 0.f, s1 = 0.f;
    int i = beg;
    for (; i + 3 < end; i += 4) {
        int sA = csrc[i], sB = csrc[i + 1], sC = csrc[i + 2], sD = csrc[i + 3];
        const float* rA = Hn + (size_t)sA * HID;
        const float* rB = Hn + (size_t)sB * HID;
        const float* rC = Hn + (size_t)sC * HID;
        const float* rD = Hn + (size_t)sD * HID;
        float a0 = __ldg(rA + lane), a1 = __ldg(rA + lane + 32);
        float b0 = __ldg(rB + lane), b1 = __ldg(rB + lane + 32);
        float c0 = __ldg(rC + lane), c1 = __ldg(rC + lane + 32);
        float d0 = __ldg(rD + lane), d1 = __ldg(rD + lane + 32);
        s0 += (a0 + b0) + (c0 + d0);
        s1 += (a1 + b1) + (c1 + d1);
    }
    for (; i < end; i++) {
        int sA = csrc[i];
        const float* rA = Hn + (size_t)sA * HID;
        s0 += __ldg(rA + lane);
        s1 += __ldg(rA + lane + 32);
    }

    float inv = g_invdeg[node];
    size_t base = (size_t)node * HID;
    float a0 = fmaxf(g_Hs[base + lane]      + s0 * inv, 0.f);
    float a1 = fmaxf(g_Hs[base + lane + 32] + s1 * inv, 0.f);
    float ss = a0 * a0 + a1 * a1;
#pragma unroll
    for (int o = 16; o > 0; o >>= 1) ss += __shfl_xor_sync(0xffffffffu, ss, o);
    float r = 1.f / (sqrtf(ss) + EPS);
    g_H[base + lane]      = a0 * r;
    g_H[base + lane + 32] = a1 * r;
}

// ---------------- MLP head: sigmoid(relu(H@mw1+mb1)@mw2+mb2) ----------------
__global__ void k_mlp(const float* __restrict__ mw1, const float* __restrict__ mb1,
                      const float* __restrict__ mw2, const float* __restrict__ mb2,
                      float* __restrict__ out) {
    __shared__ float W1[HID * 32];
    __shared__ float W2[32];
    __shared__ float B1[32];
    __shared__ float hrow[8][HID];
    int t = threadIdx.x;
    for (int i = t; i < HID * 32; i += 256) W1[i] = mw1[i];
    if (t < 32) { W2[t] = mw2[t]; B1[t] = mb1[t]; }
    __syncthreads();

    int wid = t >> 5, lane = t & 31;
    int node = blockIdx.x * 8 + wid;
    if (node >= N_NODES) return;
    size_t base = (size_t)node * HID;
    hrow[wid][lane]      = g_H[base + lane];
    hrow[wid][lane + 32] = g_H[base + lane + 32];
    __syncwarp();

    float acc = B1[lane];
    for (int k = 0; k < HID; k++) acc += hrow[wid][k] * W1[k * 32 + lane];
    acc = fmaxf(acc, 0.f) * W2[lane];
#pragma unroll
    for (int o = 16; o > 0; o >>= 1) acc += __shfl_xor_sync(0xffffffffu, acc, o);
    if (lane == 0) out[node] = 1.f / (1.f + expf(-(acc + mb2[0])));
}

// ---------------- launch (pure kernel launches; nothing else) ----------------
extern "C" void kernel_launch(void* const* d_in, const int* in_sizes, int n_in,
                              void* d_out, int out_size) {
    const float* x   = (const float*)d_in[0];
    const int*   ei  = (const int*)d_in[1];     // int32 (harness dtype set)
    const float* w0s = (const float*)d_in[2];
    const float* w0n = (const float*)d_in[3];
    const float* w1s = (const float*)d_in[4];
    const float* w1n = (const float*)d_in[5];
    const float* w2s = (const float*)d_in[6];
    const float* w2n = (const float*)d_in[7];
    const float* mw1 = (const float*)d_in[8];
    const float* mb1 = (const float*)d_in[9];
    const float* mw2 = (const float*)d_in[10];
    const float* mb2 = (const float*)d_in[11];
    float*       out = (float*)d_out;

    const int TB = 256;
    // CSR build
    k_zero_deg<<<(N_NODES + TB - 1) / TB, TB>>>();
    k_prep<<<(N_EDGES + TB - 1) / TB, TB>>>(ei);
    k_scan<<<1, 1024>>>();
    k_scatter<<<(N_EDGES + TB - 1) / TB, TB>>>();

    const int gemmBlocks = (N_NODES + 63) / 64;       // 782
    const int aggBlocks  = (N_NODES * 32 + TB - 1) / TB;

    // layer 0 (K = 128, input = x)
    k_gemm2<IN_DIM><<<gemmBlocks, TB>>>(x, w0s, w0n, 0);
    k_aggfin<<<aggBlocks, TB>>>();

    // layer 1
    k_gemm2<HID><<<gemmBlocks, TB>>>(nullptr, w1s, w1n, 1);
    k_aggfin<<<aggBlocks, TB>>>();

    // layer 2
    k_gemm2<HID><<<gemmBlocks, TB>>>(nullptr, w2s, w2n, 1);
    k_aggfin<<<aggBlocks, TB>>>();

    // MLP head
    k_mlp<<<(N_NODES + 7) / 8, TB>>>(mw1, mb1, mw2, mb2, out);
}